// round 7
// baseline (speedup 1.0000x reference)
#include <cuda_runtime.h>
#include <cuda_bf16.h>
#include <cstdint>

#define NODE_DIM 256
#define HIDDEN   128
#define MAX_NODES 100000

// ---------------- device scratch ----------------
__device__ float         g_PQ [(size_t)MAX_NODES * 256];   // P(+b1)|Q per node
__device__ __nv_bfloat16 g_Bhi[256 * 256];                  // B[n][k] = W1ab[k][n]
__device__ __nv_bfloat16 g_Blo[256 * 256];

// ---------------- helpers ----------------
__device__ __forceinline__ uint32_t smem_u32(const void* p) {
    uint32_t a;
    asm("{ .reg .u64 t; cvta.to.shared.u64 t, %1; cvt.u32.u64 %0, t; }" : "=r"(a) : "l"(p));
    return a;
}
__device__ __forceinline__ void ldsm4(uint32_t* r, uint32_t addr) {
    asm volatile("ldmatrix.sync.aligned.m8n8.x4.shared.b16 {%0,%1,%2,%3}, [%4];"
        : "=r"(r[0]), "=r"(r[1]), "=r"(r[2]), "=r"(r[3]) : "r"(addr));
}
__device__ __forceinline__ void mma_bf16(float* d, const uint32_t* a, const uint32_t* b) {
    asm volatile("mma.sync.aligned.m16n8k16.row.col.f32.bf16.bf16.f32 "
        "{%0,%1,%2,%3}, {%4,%5,%6,%7}, {%8,%9}, {%0,%1,%2,%3};"
        : "+f"(d[0]), "+f"(d[1]), "+f"(d[2]), "+f"(d[3])
        : "r"(a[0]), "r"(a[1]), "r"(a[2]), "r"(a[3]), "r"(b[0]), "r"(b[1]));
}
#define SW128(o) ((o) ^ (((o) >> 3) & 0x70))

union BP4 { __nv_bfloat16 b[4]; uint2 u; };
__device__ __forceinline__ void split4(const float4& v, uint2& uh, uint2& ul) {
    float x[4] = {v.x, v.y, v.z, v.w};
    BP4 hi, lo;
    #pragma unroll
    for (int t = 0; t < 4; t++) {
        hi.b[t] = __float2bfloat16(x[t]);
        lo.b[t] = __float2bfloat16(x[t] - __bfloat162float(hi.b[t]));
    }
    uh = hi.u; ul = lo.u;
}

// ---------------------------------------------------------------------------
// conv_B: B[n][k] bf16 hi/lo.  n<128 -> W1[k][n]; n>=128 -> W1[256+k][n-128]
// ---------------------------------------------------------------------------
__global__ void conv_B_kernel(const float* __restrict__ W1) {
    int idx = blockIdx.x * blockDim.x + threadIdx.x;   // 0..65535
    int n = idx >> 8, k = idx & 255;
    float w = (n < HIDDEN) ? W1[(size_t)k * HIDDEN + n]
                           : W1[(size_t)(256 + k) * HIDDEN + (n - HIDDEN)];
    __nv_bfloat16 hi = __float2bfloat16(w);
    __nv_bfloat16 lo = __float2bfloat16(w - __bfloat162float(hi));
    g_Bhi[idx] = hi;
    g_Blo[idx] = lo;
}

// ---------------------------------------------------------------------------
// Phase 1: PQ = z @ [W1a|W1b] via mma.sync bf16 3-term split, fused z convert.
// b1 folded into the P half.
// ---------------------------------------------------------------------------
#define SA_HI 0
#define SA_LO 16384
#define SB_HI 32768
#define SB_LO 49152
#define GSMEM 65536

__global__ __launch_bounds__(256, 2) void gemm_tc_kernel(
    const float* __restrict__ z, const float* __restrict__ b1, int M)
{
    extern __shared__ char smem[];
    const uint32_t sb = smem_u32(smem);
    const int tid  = threadIdx.x;
    const int warp = tid >> 5;
    const int lane = tid & 31;
    const int m0   = blockIdx.x * 128;

    const uint32_t a_row  = warp * 16 + ((lane >> 3) & 1) * 8 + (lane & 7);
    const uint32_t a_koff = (lane >> 4) * 16;
    const uint32_t b_rowi = ((lane >> 4) & 1) * 8 + (lane & 7);
    const uint32_t b_koff = ((lane >> 3) & 1) * 16;

    #pragma unroll 1
    for (int nh = 0; nh < 2; nh++) {
        float acc[16][4];
        #pragma unroll
        for (int i = 0; i < 16; i++)
            #pragma unroll
            for (int j = 0; j < 4; j++) acc[i][j] = 0.f;

        #pragma unroll 1
        for (int ch = 0; ch < 4; ch++) {
            const int kc = ch * 64;
            __syncthreads();
            #pragma unroll
            for (int j = 0; j < 8; j++) {
                int id = j * 256 + tid;
                int r = id >> 4, c = id & 15;
                float4 v = make_float4(0.f, 0.f, 0.f, 0.f);
                if (m0 + r < M)
                    v = *(const float4*)(z + (size_t)(m0 + r) * 256 + kc + c * 4);
                uint2 uh, ul;
                split4(v, uh, ul);
                uint32_t so = SW128((uint32_t)(r * 128 + c * 8));
                *(uint2*)(smem + SA_HI + so) = uh;
                *(uint2*)(smem + SA_LO + so) = ul;
            }
            #pragma unroll
            for (int j = 0; j < 4; j++) {
                int id = j * 256 + tid;
                int r = id >> 3, c = id & 7;
                size_t off = (size_t)(nh * 128 + r) * 256 + kc + c * 8;
                uint4 vh = *(const uint4*)(g_Bhi + off);
                uint4 vl = *(const uint4*)(g_Blo + off);
                uint32_t so = SW128((uint32_t)(r * 128 + c * 16));
                *(uint4*)(smem + SB_HI + so) = vh;
                *(uint4*)(smem + SB_LO + so) = vl;
            }
            __syncthreads();

            #pragma unroll
            for (int kt = 0; kt < 4; kt++) {
                uint32_t ah[4], al[4];
                uint32_t aoff = SW128(a_row * 128 + kt * 32 + a_koff);
                ldsm4(ah, sb + SA_HI + aoff);
                ldsm4(al, sb + SA_LO + aoff);
                #pragma unroll
                for (int ntp = 0; ntp < 8; ntp++) {
                    uint32_t boff = SW128((ntp * 16 + b_rowi) * 128 + kt * 32 + b_koff);
                    uint32_t bh[4], bl[4];
                    ldsm4(bh, sb + SB_HI + boff);
                    ldsm4(bl, sb + SB_LO + boff);
                    mma_bf16(acc[2 * ntp],     ah, bh);
                    mma_bf16(acc[2 * ntp],     ah, bl);
                    mma_bf16(acc[2 * ntp],     al, bh);
                    mma_bf16(acc[2 * ntp + 1], ah, bh + 2);
                    mma_bf16(acc[2 * ntp + 1], ah, bl + 2);
                    mma_bf16(acc[2 * ntp + 1], al, bh + 2);
                }
            }
        }

        const int r0 = m0 + warp * 16 + (lane >> 2);
        const int cb = 2 * (lane & 3);
        #pragma unroll
        for (int nt = 0; nt < 16; nt++) {
            int ncol = cb + nt * 8;
            float2 bb = make_float2(0.f, 0.f);
            if (nh == 0) bb = __ldg((const float2*)(b1 + ncol));
            int n0 = nh * 128 + ncol;
            if (r0 < M)
                *(float2*)(g_PQ + (size_t)r0 * 256 + n0) =
                    make_float2(acc[nt][0] + bb.x, acc[nt][1] + bb.y);
            if (r0 + 8 < M)
                *(float2*)(g_PQ + (size_t)(r0 + 8) * 256 + n0) =
                    make_float2(acc[nt][2] + bb.x, acc[nt][3] + bb.y);
        }
        __syncthreads();
    }
}

// ---------------------------------------------------------------------------
// Phase 2: 128-edge tiles. ea@W1c on tensor cores (bf16 3-term split in-kernel),
// acc transposed through warp-private smem (stride 136: conflict-free),
// epilogue = one edge per warp iter: warp-wide LDG.128 gathers of P/Q rows.
// ---------------------------------------------------------------------------
#define TE 128
// dynamic smem layout (bytes)
#define ES_AH   0
#define ES_AL   10240
#define ES_WH   20480
#define ES_WL   30720
#define ES_ACC  40960                      // 64 rows x 136 floats
#define ES_S    (40960 + 34816)            // 75776
#define ES_D    (75776 + 512)              // 76288
#define ESMEM   (76288 + 512)              // 76800

__global__ __launch_bounds__(256, 2) void edge_kernel(
    const int* __restrict__ eli, const float* __restrict__ ea,
    const float* __restrict__ W1, const float* __restrict__ W2,
    const float* __restrict__ b2, float* __restrict__ out, int E)
{
    extern __shared__ char es[];
    __nv_bfloat16* sAh = (__nv_bfloat16*)(es + ES_AH);
    __nv_bfloat16* sAl = (__nv_bfloat16*)(es + ES_AL);
    __nv_bfloat16* sWh = (__nv_bfloat16*)(es + ES_WH);
    __nv_bfloat16* sWl = (__nv_bfloat16*)(es + ES_WL);
    float*         sAcc = (float*)(es + ES_ACC);
    int*           sS  = (int*)(es + ES_S);
    int*           sD  = (int*)(es + ES_D);

    const int tid  = threadIdx.x;
    const int warp = tid >> 5;
    const int lane = tid & 31;

    // One-time: W1c -> sW[n][k] hi/lo (rows of 40 bf16)
    #pragma unroll
    for (int j = 0; j < 16; j++) {
        int id = j * 256 + tid;            // 0..4095
        int k = id >> 7, n = id & 127;
        float w = W1[(size_t)(512 + k) * HIDDEN + n];
        __nv_bfloat16 hi = __float2bfloat16(w);
        sWh[n * 40 + k] = hi;
        sWl[n * 40 + k] = __float2bfloat16(w - __bfloat162float(hi));
    }
    const float4 w2v = __ldg((const float4*)(W2 + lane * 4));
    const float  b2v = b2[0];

    const uint32_t sbAh = smem_u32(sAh), sbAl = smem_u32(sAl);
    const uint32_t sbWh = smem_u32(sWh), sbWl = smem_u32(sWl);

    const uint32_t a_row  = warp * 16 + ((lane >> 3) & 1) * 8 + (lane & 7);
    const uint32_t a_koff = (lane >> 4) * 16;
    const uint32_t b_rowi = ((lane >> 4) & 1) * 8 + (lane & 7);
    const uint32_t b_koff = ((lane >> 3) & 1) * 16;
    const int cb = 2 * (lane & 3);

    const int ntiles = (E + TE - 1) / TE;

    for (int tile = blockIdx.x; tile < ntiles; tile += gridDim.x) {
        const int e0 = tile * TE;
        __syncthreads();   // previous tile's epilogue (sS/sD readers) done

        if (tid < TE) {
            int e = e0 + tid;
            sS[tid] = (e < E) ? eli[e] : 0;
        } else {
            int e = e0 + (tid - TE);
            sD[tid - TE] = (e < E) ? eli[(size_t)E + e] : 0;
        }

        // EA tile fp32 -> bf16 hi/lo, rows of 40 bf16
        #pragma unroll
        for (int j = 0; j < 4; j++) {
            int id = j * 256 + tid;
            int e = id >> 3, c4 = id & 7;
            float4 v = make_float4(0.f, 0.f, 0.f, 0.f);
            if (e0 + e < E)
                v = *(const float4*)(ea + (size_t)(e0 + e) * 32 + c4 * 4);
            uint2 uh, ul;
            split4(v, uh, ul);
            *(uint2*)(sAh + e * 40 + c4 * 4) = uh;
            *(uint2*)(sAl + e * 40 + c4 * 4) = ul;
        }
        __syncthreads();

        // Tensor GEMM: D[128e x 128n] = EA @ W1c, 3-term split
        float acc[16][4];
        #pragma unroll
        for (int i = 0; i < 16; i++)
            #pragma unroll
            for (int j = 0; j < 4; j++) acc[i][j] = 0.f;

        #pragma unroll
        for (int kt = 0; kt < 2; kt++) {
            uint32_t ah[4], al[4];
            uint32_t aoff = a_row * 80 + kt * 32 + a_koff;
            ldsm4(ah, sbAh + aoff);
            ldsm4(al, sbAl + aoff);
            #pragma unroll
            for (int ntp = 0; ntp < 8; ntp++) {
                uint32_t boff = (ntp * 16 + b_rowi) * 80 + kt * 32 + b_koff;
                uint32_t bh[4], bl[4];
                ldsm4(bh, sbWh + boff);
                ldsm4(bl, sbWl + boff);
                mma_bf16(acc[2 * ntp],     ah, bh);
                mma_bf16(acc[2 * ntp],     ah, bl);
                mma_bf16(acc[2 * ntp],     al, bh);
                mma_bf16(acc[2 * ntp + 1], ah, bh + 2);
                mma_bf16(acc[2 * ntp + 1], ah, bl + 2);
                mma_bf16(acc[2 * ntp + 1], al, bh + 2);
            }
        }

        // Epilogue: 2 passes; warp-private acc transpose then warp-wide gathers
        #pragma unroll 1
        for (int pass = 0; pass < 2; pass++) {
            // store acc rows (eloc = warp*16 + (lane>>2) + 8*pass) to slot warp*8+(lane>>2)
            float* dstrow = sAcc + (size_t)(warp * 8 + (lane >> 2)) * 136 + cb;
            #pragma unroll
            for (int nt = 0; nt < 16; nt++)
                *(float2*)(dstrow + nt * 8) =
                    make_float2(acc[nt][2 * pass], acc[nt][2 * pass + 1]);
            __syncwarp();

            const int ebase = warp * 16 + 8 * pass;
            #pragma unroll 1
            for (int j = 0; j < 8; j++) {
                int eloc = ebase + j;
                int e    = e0 + eloc;
                int s    = sS[eloc];
                int d    = sD[eloc];
                float4 a4 = *(const float4*)(sAcc + (size_t)(warp * 8 + j) * 136 + lane * 4);
                float4 p4 = __ldg((const float4*)(g_PQ + (size_t)s * 256 + lane * 4));
                float4 q4 = __ldg((const float4*)(g_PQ + (size_t)d * 256 + 128 + lane * 4));

                float h0 = fmaxf(a4.x + p4.x + q4.x, 0.f);
                float h1 = fmaxf(a4.y + p4.y + q4.y, 0.f);
                float h2 = fmaxf(a4.z + p4.z + q4.z, 0.f);
                float h3 = fmaxf(a4.w + p4.w + q4.w, 0.f);

                float part = fmaf(h0, w2v.x, fmaf(h1, w2v.y,
                             fmaf(h2, w2v.z, h3 * w2v.w)));

                part += __shfl_xor_sync(0xffffffffu, part, 16);
                part += __shfl_xor_sync(0xffffffffu, part, 8);
                part += __shfl_xor_sync(0xffffffffu, part, 4);
                part += __shfl_xor_sync(0xffffffffu, part, 2);
                part += __shfl_xor_sync(0xffffffffu, part, 1);

                if (lane == 0 && e < E)
                    out[e] = part + b2v;
            }
            __syncwarp();
        }
    }
}

// ---------------------------------------------------------------------------
extern "C" void kernel_launch(void* const* d_in, const int* in_sizes, int n_in,
                              void* d_out, int out_size) {
    const float* z   = (const float*)d_in[0];
    const int*   eli = (const int*)d_in[1];      // int32 (JAX canonicalized)
    const float* ea  = (const float*)d_in[2];
    const float* W1  = (const float*)d_in[3];
    const float* b1  = (const float*)d_in[4];
    const float* W2  = (const float*)d_in[5];
    const float* b2  = (const float*)d_in[6];
    float* out = (float*)d_out;

    int M = in_sizes[0] / NODE_DIM;   // 100000
    int E = out_size;                 // 1000000

    cudaFuncSetAttribute(gemm_tc_kernel,
                         cudaFuncAttributeMaxDynamicSharedMemorySize, GSMEM);
    cudaFuncSetAttribute(edge_kernel,
                         cudaFuncAttributeMaxDynamicSharedMemorySize, ESMEM);

    conv_B_kernel<<<256, 256>>>(W1);

    int gblocks = (M + 127) / 128;
    gemm_tc_kernel<<<gblocks, 256, GSMEM>>>(z, b1, M);

    int ntiles = (E + TE - 1) / TE;
    int nblk = ntiles < 296 ? ntiles : 296;
    edge_kernel<<<nblk, 256, ESMEM>>>(eli, ea, W1, W2, b2, out, E);
}

// round 8
// speedup vs baseline: 1.6986x; 1.6986x over previous
#include <cuda_runtime.h>
#include <cuda_bf16.h>
#include <cstdint>

#define NODE_DIM 256
#define HIDDEN   128
#define MAX_NODES 100000

// ---------------- device scratch ----------------
__device__ float         g_PQ [(size_t)MAX_NODES * 256];   // P(+b1)|Q per node
__device__ __nv_bfloat16 g_Bhi[256 * 256];                  // B[n][k] = W1ab[k][n]
__device__ __nv_bfloat16 g_Blo[256 * 256];

// ---------------- helpers ----------------
__device__ __forceinline__ uint32_t smem_u32(const void* p) {
    uint32_t a;
    asm("{ .reg .u64 t; cvta.to.shared.u64 t, %1; cvt.u32.u64 %0, t; }" : "=r"(a) : "l"(p));
    return a;
}
__device__ __forceinline__ void ldsm4(uint32_t* r, uint32_t addr) {
    asm volatile("ldmatrix.sync.aligned.m8n8.x4.shared.b16 {%0,%1,%2,%3}, [%4];"
        : "=r"(r[0]), "=r"(r[1]), "=r"(r[2]), "=r"(r[3]) : "r"(addr));
}
__device__ __forceinline__ void mma_bf16(float* d, const uint32_t* a, const uint32_t* b) {
    asm volatile("mma.sync.aligned.m16n8k16.row.col.f32.bf16.bf16.f32 "
        "{%0,%1,%2,%3}, {%4,%5,%6,%7}, {%8,%9}, {%0,%1,%2,%3};"
        : "+f"(d[0]), "+f"(d[1]), "+f"(d[2]), "+f"(d[3])
        : "r"(a[0]), "r"(a[1]), "r"(a[2]), "r"(a[3]), "r"(b[0]), "r"(b[1]));
}
#define SW128(o) ((o) ^ (((o) >> 3) & 0x70))

union BP4 { __nv_bfloat16 b[4]; uint2 u; };
__device__ __forceinline__ void split4(const float4& v, uint2& uh, uint2& ul) {
    float x[4] = {v.x, v.y, v.z, v.w};
    BP4 hi, lo;
    #pragma unroll
    for (int t = 0; t < 4; t++) {
        hi.b[t] = __float2bfloat16(x[t]);
        lo.b[t] = __float2bfloat16(x[t] - __bfloat162float(hi.b[t]));
    }
    uh = hi.u; ul = lo.u;
}

// ---------------------------------------------------------------------------
// conv_B: B[n][k] bf16 hi/lo.  n<128 -> W1[k][n]; n>=128 -> W1[256+k][n-128]
// ---------------------------------------------------------------------------
__global__ void conv_B_kernel(const float* __restrict__ W1) {
    int idx = blockIdx.x * blockDim.x + threadIdx.x;   // 0..65535
    int n = idx >> 8, k = idx & 255;
    float w = (n < HIDDEN) ? W1[(size_t)k * HIDDEN + n]
                           : W1[(size_t)(256 + k) * HIDDEN + (n - HIDDEN)];
    __nv_bfloat16 hi = __float2bfloat16(w);
    __nv_bfloat16 lo = __float2bfloat16(w - __bfloat162float(hi));
    g_Bhi[idx] = hi;
    g_Blo[idx] = lo;
}

// ---------------------------------------------------------------------------
// Phase 1: PQ = z @ [W1a|W1b], mma.sync bf16 3-term split, fused z convert.
// SINGLE K-pass: CTA = 128 rows x 512 threads; 16 warps = 8 m-tiles x 2 halves.
// Both B halves resident in smem. b1 folded into P half.
// ---------------------------------------------------------------------------
#define SA_HI 0
#define SA_LO 16384
#define SB_HI 32768
#define SB_LO 65536
#define GSMEM 98304

__global__ __launch_bounds__(512, 1) void gemm_tc_kernel(
    const float* __restrict__ z, const float* __restrict__ b1, int M)
{
    extern __shared__ char smem[];
    const uint32_t sb = smem_u32(smem);
    const int tid  = threadIdx.x;
    const int warp = tid >> 5;
    const int lane = tid & 31;
    const int half = warp >> 3;           // 0: cols 0..127, 1: cols 128..255
    const int wm   = warp & 7;            // m-tile within CTA (16 rows)
    const int m0   = blockIdx.x * 128;

    const uint32_t a_row  = wm * 16 + ((lane >> 3) & 1) * 8 + (lane & 7);
    const uint32_t a_koff = (lane >> 4) * 16;
    const uint32_t b_rowi = ((lane >> 4) & 1) * 8 + (lane & 7);
    const uint32_t b_koff = ((lane >> 3) & 1) * 16;

    float acc[16][4];
    #pragma unroll
    for (int i = 0; i < 16; i++)
        #pragma unroll
        for (int j = 0; j < 4; j++) acc[i][j] = 0.f;

    #pragma unroll 1
    for (int ch = 0; ch < 4; ch++) {
        const int kc = ch * 64;
        __syncthreads();
        // A: z fp32 (128 x 64) -> bf16 hi/lo in-kernel, SW128 rows of 128B
        #pragma unroll
        for (int j = 0; j < 4; j++) {
            int id = j * 512 + tid;        // 0..2047 float4 slots
            int r = id >> 4, c = id & 15;
            float4 v = make_float4(0.f, 0.f, 0.f, 0.f);
            if (m0 + r < M)
                v = *(const float4*)(z + (size_t)(m0 + r) * 256 + kc + c * 4);
            uint2 uh, ul;
            split4(v, uh, ul);
            uint32_t so = SW128((uint32_t)(r * 128 + c * 8));
            *(uint2*)(smem + SA_HI + so) = uh;
            *(uint2*)(smem + SA_LO + so) = ul;
        }
        // B: both halves, 256 n-rows x 64 k bf16 hi/lo
        #pragma unroll
        for (int j = 0; j < 4; j++) {
            int id = j * 512 + tid;        // 0..2047 uint4 slots
            int r = id >> 3, c = id & 7;
            size_t off = (size_t)r * 256 + kc + c * 8;
            uint4 vh = *(const uint4*)(g_Bhi + off);
            uint4 vl = *(const uint4*)(g_Blo + off);
            uint32_t so = SW128((uint32_t)(r * 128 + c * 16));
            *(uint4*)(smem + SB_HI + so) = vh;
            *(uint4*)(smem + SB_LO + so) = vl;
        }
        __syncthreads();

        #pragma unroll
        for (int kt = 0; kt < 4; kt++) {
            uint32_t ah[4], al[4];
            uint32_t aoff = SW128(a_row * 128 + kt * 32 + a_koff);
            ldsm4(ah, sb + SA_HI + aoff);
            ldsm4(al, sb + SA_LO + aoff);
            #pragma unroll
            for (int ntp = 0; ntp < 8; ntp++) {
                uint32_t boff = SW128((uint32_t)((half * 128 + ntp * 16 + b_rowi) * 128
                                                 + kt * 32 + b_koff));
                uint32_t bh[4], bl[4];
                ldsm4(bh, sb + SB_HI + boff);
                ldsm4(bl, sb + SB_LO + boff);
                mma_bf16(acc[2 * ntp],     ah, bh);
                mma_bf16(acc[2 * ntp],     ah, bl);
                mma_bf16(acc[2 * ntp],     al, bh);
                mma_bf16(acc[2 * ntp + 1], ah, bh + 2);
                mma_bf16(acc[2 * ntp + 1], ah, bl + 2);
                mma_bf16(acc[2 * ntp + 1], al, bh + 2);
            }
        }
    }

    // Epilogue: +b1 on P half, write g_PQ
    const int r0 = m0 + wm * 16 + (lane >> 2);
    const int cb = 2 * (lane & 3);
    #pragma unroll
    for (int nt = 0; nt < 16; nt++) {
        int ncol = cb + nt * 8;                 // col within this half
        float2 bb = make_float2(0.f, 0.f);
        if (half == 0) bb = __ldg((const float2*)(b1 + ncol));
        int n0 = half * 128 + ncol;
        if (r0 < M)
            *(float2*)(g_PQ + (size_t)r0 * 256 + n0) =
                make_float2(acc[nt][0] + bb.x, acc[nt][1] + bb.y);
        if (r0 + 8 < M)
            *(float2*)(g_PQ + (size_t)(r0 + 8) * 256 + n0) =
                make_float2(acc[nt][2] + bb.x, acc[nt][3] + bb.y);
    }
}

// ---------------------------------------------------------------------------
// Phase 2 (reverted to R6): 128-edge tiles. ea@W1c on tensor cores,
// fused per-quad gather epilogue (b1 already folded into P).
// ---------------------------------------------------------------------------
#define TE 128

__global__ __launch_bounds__(256, 2) void edge_kernel(
    const int* __restrict__ eli, const float* __restrict__ ea,
    const float* __restrict__ W1, const float* __restrict__ W2,
    const float* __restrict__ b2, float* __restrict__ out, int E)
{
    __shared__ __align__(16) __nv_bfloat16 sAh[128 * 40];
    __shared__ __align__(16) __nv_bfloat16 sAl[128 * 40];
    __shared__ __align__(16) __nv_bfloat16 sWh[128 * 40];
    __shared__ __align__(16) __nv_bfloat16 sWl[128 * 40];
    __shared__ float sW2[128];
    __shared__ int   sS[TE];
    __shared__ int   sD[TE];

    const int tid  = threadIdx.x;
    const int warp = tid >> 5;
    const int lane = tid & 31;

    #pragma unroll
    for (int j = 0; j < 16; j++) {
        int id = j * 256 + tid;            // 0..4095
        int k = id >> 7, n = id & 127;
        float w = W1[(size_t)(512 + k) * HIDDEN + n];
        __nv_bfloat16 hi = __float2bfloat16(w);
        sWh[n * 40 + k] = hi;
        sWl[n * 40 + k] = __float2bfloat16(w - __bfloat162float(hi));
    }
    if (tid < 128) sW2[tid] = W2[tid];
    const float b2v = b2[0];

    const uint32_t sbAh = smem_u32(sAh), sbAl = smem_u32(sAl);
    const uint32_t sbWh = smem_u32(sWh), sbWl = smem_u32(sWl);

    const uint32_t a_row  = warp * 16 + ((lane >> 3) & 1) * 8 + (lane & 7);
    const uint32_t a_koff = (lane >> 4) * 16;
    const uint32_t b_rowi = ((lane >> 4) & 1) * 8 + (lane & 7);
    const uint32_t b_koff = ((lane >> 3) & 1) * 16;
    const int cb = 2 * (lane & 3);

    const int ntiles = (E + TE - 1) / TE;

    for (int tile = blockIdx.x; tile < ntiles; tile += gridDim.x) {
        const int e0 = tile * TE;
        __syncthreads();

        if (tid < TE) {
            int e = e0 + tid;
            sS[tid] = (e < E) ? eli[e] : 0;
        } else {
            int e = e0 + (tid - TE);
            sD[tid - TE] = (e < E) ? eli[(size_t)E + e] : 0;
        }

        #pragma unroll
        for (int j = 0; j < 4; j++) {
            int id = j * 256 + tid;
            int e = id >> 3, c4 = id & 7;
            float4 v = make_float4(0.f, 0.f, 0.f, 0.f);
            if (e0 + e < E)
                v = *(const float4*)(ea + (size_t)(e0 + e) * 32 + c4 * 4);
            uint2 uh, ul;
            split4(v, uh, ul);
            *(uint2*)(sAh + e * 40 + c4 * 4) = uh;
            *(uint2*)(sAl + e * 40 + c4 * 4) = ul;
        }
        __syncthreads();

        float acc[16][4];
        #pragma unroll
        for (int i = 0; i < 16; i++)
            #pragma unroll
            for (int j = 0; j < 4; j++) acc[i][j] = 0.f;

        #pragma unroll
        for (int kt = 0; kt < 2; kt++) {
            uint32_t ah[4], al[4];
            uint32_t aoff = a_row * 80 + kt * 32 + a_koff;
            ldsm4(ah, sbAh + aoff);
            ldsm4(al, sbAl + aoff);
            #pragma unroll
            for (int ntp = 0; ntp < 8; ntp++) {
                uint32_t boff = (ntp * 16 + b_rowi) * 80 + kt * 32 + b_koff;
                uint32_t bh[4], bl[4];
                ldsm4(bh, sbWh + boff);
                ldsm4(bl, sbWl + boff);
                mma_bf16(acc[2 * ntp],     ah, bh);
                mma_bf16(acc[2 * ntp],     ah, bl);
                mma_bf16(acc[2 * ntp],     al, bh);
                mma_bf16(acc[2 * ntp + 1], ah, bh + 2);
                mma_bf16(acc[2 * ntp + 1], ah, bl + 2);
                mma_bf16(acc[2 * ntp + 1], al, bh + 2);
            }
        }

        #pragma unroll
        for (int i = 0; i < 2; i++) {
            int eloc = warp * 16 + (lane >> 2) + 8 * i;
            int e    = e0 + eloc;
            int s    = sS[eloc];
            int d    = sD[eloc];
            const float* pb = g_PQ + (size_t)s * 256;
            const float* qb = g_PQ + (size_t)d * 256 + 128;
            float part = 0.f;
            #pragma unroll
            for (int nt = 0; nt < 16; nt++) {
                int col = nt * 8 + cb;
                float2 p  = __ldg((const float2*)(pb + col));
                float2 q  = __ldg((const float2*)(qb + col));
                float2 w2 = *(const float2*)(&sW2[col]);
                float h0 = fmaxf(acc[nt][2 * i]     + p.x + q.x, 0.f);
                float h1 = fmaxf(acc[nt][2 * i + 1] + p.y + q.y, 0.f);
                part = fmaf(h0, w2.x, fmaf(h1, w2.y, part));
            }
            part += __shfl_xor_sync(0xffffffffu, part, 1);
            part += __shfl_xor_sync(0xffffffffu, part, 2);
            if ((lane & 3) == 0 && e < E)
                out[e] = part + b2v;
        }
    }
}

// ---------------------------------------------------------------------------
extern "C" void kernel_launch(void* const* d_in, const int* in_sizes, int n_in,
                              void* d_out, int out_size) {
    const float* z   = (const float*)d_in[0];
    const int*   eli = (const int*)d_in[1];      // int32 (JAX canonicalized)
    const float* ea  = (const float*)d_in[2];
    const float* W1  = (const float*)d_in[3];
    const float* b1  = (const float*)d_in[4];
    const float* W2  = (const float*)d_in[5];
    const float* b2  = (const float*)d_in[6];
    float* out = (float*)d_out;

    int M = in_sizes[0] / NODE_DIM;   // 100000
    int E = out_size;                 // 1000000

    cudaFuncSetAttribute(gemm_tc_kernel,
                         cudaFuncAttributeMaxDynamicSharedMemorySize, GSMEM);

    conv_B_kernel<<<256, 256>>>(W1);

    int gblocks = (M + 127) / 128;
    gemm_tc_kernel<<<gblocks, 512, GSMEM>>>(z, b1, M);

    int ntiles = (E + TE - 1) / TE;
    int nblk = ntiles < 296 ? ntiles : 296;
    edge_kernel<<<nblk, 256>>>(eli, ea, W1, W2, b2, out, E);
}